// round 14
// baseline (speedup 1.0000x reference)
#include <cuda_runtime.h>
#include <cuda_bf16.h>
#include <math.h>
#include <stdint.h>

#define NB 2
#define CC 8192
#define HID 4096
#define RDIM 512
#define HH 8
#define DD 128
#define TOPK 16
#define NROWS (NB*CC)

// -------- device scratch --------
__device__ __align__(128) uint8_t g_bpack[(size_t)2 * 64 * 65536];
__device__ float g_q[(size_t)NROWS * RDIM];

// -------- helpers --------
__device__ __forceinline__ unsigned long long pk4(float a, float b, float c, float d) {
    return (unsigned long long)__bfloat16_as_ushort(__float2bfloat16_rn(a))
         | ((unsigned long long)__bfloat16_as_ushort(__float2bfloat16_rn(b)) << 16)
         | ((unsigned long long)__bfloat16_as_ushort(__float2bfloat16_rn(c)) << 32)
         | ((unsigned long long)__bfloat16_as_ushort(__float2bfloat16_rn(d)) << 48);
}
__device__ __forceinline__ float resid(float v) {
    return v - __bfloat162float(__float2bfloat16_rn(v));
}
__device__ __forceinline__ void ldm_x4(uint32_t* r, uint32_t addr) {
    asm volatile("ldmatrix.sync.aligned.m8n8.x4.shared.b16 {%0,%1,%2,%3}, [%4];"
                 : "=r"(r[0]), "=r"(r[1]), "=r"(r[2]), "=r"(r[3]) : "r"(addr));
}
__device__ __forceinline__ void mma16816(float* d, const uint32_t* a, const uint32_t* b) {
    asm volatile("mma.sync.aligned.m16n8k16.row.col.f32.bf16.bf16.f32 "
                 "{%0,%1,%2,%3}, {%4,%5,%6,%7}, {%8,%9}, {%0,%1,%2,%3};"
                 : "+f"(d[0]), "+f"(d[1]), "+f"(d[2]), "+f"(d[3])
                 : "r"(a[0]), "r"(a[1]), "r"(a[2]), "r"(a[3]), "r"(b[0]), "r"(b[1]));
}
__device__ __forceinline__ void mbar_wait(uint32_t a, uint32_t ph) {
    asm volatile("{\n\t.reg .pred P;\n\tWL%=:\n\t"
                 "mbarrier.try_wait.parity.acquire.cta.shared::cta.b64 P, [%0], %1, 0x989680;\n\t"
                 "@!P bra WL%=;\n\t}" :: "r"(a), "r"(ph) : "memory");
}
__device__ __forceinline__ void mbar_arrive(uint32_t a) {
    asm volatile("mbarrier.arrive.shared.b64 _, [%0];" :: "r"(a) : "memory");
}
__device__ __forceinline__ void bulk_ld(uint32_t dst, const void* src, uint32_t bytes, uint32_t mbar) {
    asm volatile("cp.async.bulk.shared::cluster.global.mbarrier::complete_tx::bytes "
                 "[%0], [%1], %2, [%3];" :: "r"(dst), "l"(src), "r"(bytes), "r"(mbar) : "memory");
}

// ============================================================
// Kernel 1: fold prew into W rows, split -> packed B blocks
// ============================================================
__global__ __launch_bounds__(256) void split_b_kernel(const float* __restrict__ W,
                                                      const float* __restrict__ prew) {
    const int row = blockIdx.x;
    const int ntile = row >> 8;
    const int r = row & 255;
    const uint32_t rx = (uint32_t)(r & 7);
    const float4* wr = (const float4*)(W + (size_t)row * HID);
    const float4* pr = (const float4*)prew;
#pragma unroll
    for (int i = 0; i < 4; i++) {
        const int f = threadIdx.x + i * 256;
        float4 w = wr[f], p = pr[f];
        w.x *= p.x; w.y *= p.y; w.z *= p.z; w.w *= p.w;
        const int stage = f >> 4;
        const uint32_t c = (uint32_t)((f >> 1) & 7);
        const uint32_t sub = (uint32_t)((f & 1) * 8);
        size_t base = ((size_t)(ntile * 64 + stage)) * 65536
                    + (uint32_t)(r * 128) + ((c ^ rx) << 4) + sub;
        *(unsigned long long*)(g_bpack + base)         = pk4(w.x, w.y, w.z, w.w);
        *(unsigned long long*)(g_bpack + base + 32768) = pk4(resid(w.x), resid(w.y), resid(w.z), resid(w.w));
    }
}

// ============================================================
// Kernel 2: warp-specialized HMMA bf16x3 GEMM.
// 8 consumer warps (MMA) + 2 producer warps (bulk-load + convert A).
// smem: [0,32K) raw fp32 A | [32K,96K) abf[2] (hi 16K | lo 16K each)
//       [96K,224K) B[2] (hi 32K | lo 32K each)
// ============================================================
#define RAW_OFF 0
#define ABF_OFF 32768
#define B_OFF   98304
#define SMEM_REQ 229376
#define NSTAGES 64
#define NTHR 320

__global__ void __launch_bounds__(NTHR, 1) gemm_hmma_kernel(const float* __restrict__ hidden) {
    extern __shared__ __align__(128) uint8_t sm[];
    __shared__ __align__(8) uint64_t s_mb[7];   // 0:mbA 1,2:mbB 3,4:fullA 5,6:emptyA
    __shared__ float s_scale[128];
    const uint32_t smb = (uint32_t)__cvta_generic_to_shared(sm);
    const uint32_t mbA    = (uint32_t)__cvta_generic_to_shared(&s_mb[0]);
    const uint32_t mbB    = mbA + 8;    // [0],[1] at +8,+16
    const uint32_t fullA  = mbA + 24;   // +24,+32
    const uint32_t emptyA = mbA + 40;   // +40,+48
    const int tid = threadIdx.x;
    const int lane = tid & 31;
    const int wid = tid >> 5;
    const int mtile = blockIdx.y;
    const int ntile = blockIdx.x;
    const int m0 = mtile * 128;
    const int n0 = ntile * 256;

    if (tid == 0) {
        asm volatile("mbarrier.init.shared.b64 [%0], 64;"  :: "r"(mbA) : "memory");
        asm volatile("mbarrier.init.shared.b64 [%0], 1;"   :: "r"(mbB) : "memory");
        asm volatile("mbarrier.init.shared.b64 [%0], 1;"   :: "r"(mbB + 8) : "memory");
        asm volatile("mbarrier.init.shared.b64 [%0], 64;"  :: "r"(fullA) : "memory");
        asm volatile("mbarrier.init.shared.b64 [%0], 64;"  :: "r"(fullA + 8) : "memory");
        asm volatile("mbarrier.init.shared.b64 [%0], 256;" :: "r"(emptyA) : "memory");
        asm volatile("mbarrier.init.shared.b64 [%0], 256;" :: "r"(emptyA + 8) : "memory");
    }
    __syncthreads();

    if (wid < 8) {
        // ================= CONSUMERS (256 threads) =================
        const int wm = (wid & 1) * 64;
        const int wn = (wid >> 1) * 64;
        float acc[4][8][4];
#pragma unroll
        for (int i = 0; i < 4; i++)
#pragma unroll
            for (int j = 0; j < 8; j++)
#pragma unroll
                for (int q = 0; q < 4; q++) acc[i][j][q] = 0.f;

        auto issue_b = [&](int s) {
            const uint32_t mb = mbB + (uint32_t)((s & 1) * 8);
            asm volatile("mbarrier.arrive.expect_tx.shared.b64 _, [%0], %1;"
                         :: "r"(mb), "r"(65536u) : "memory");
            bulk_ld(smb + B_OFF + (uint32_t)((s & 1) * 65536),
                    g_bpack + ((size_t)(ntile * 64 + s)) * 65536, 65536u, mb);
        };
        if (tid == 0) issue_b(0);

        const int a_row = lane & 15;
        const int a_cs  = lane >> 4;
        const int b_row = (lane & 7) + ((lane >> 4) << 3);
        const int b_cs  = (lane >> 3) & 1;
        const int sxor  = lane & 7;

        for (int s = 0; s < NSTAGES; s++) {
            if (tid == 0 && s + 1 < NSTAGES) issue_b(s + 1);
            mbar_wait(fullA + (uint32_t)((s & 1) * 8), (uint32_t)((s >> 1) & 1));
            mbar_wait(mbB   + (uint32_t)((s & 1) * 8), (uint32_t)((s >> 1) & 1));

            const uint32_t abf = smb + ABF_OFF + (uint32_t)((s & 1) * 32768);
            const uint32_t ah_base = abf + (uint32_t)((wm + a_row) * 128);
            const uint32_t al_base = ah_base + 16384;
            const uint32_t bb = smb + B_OFF + (uint32_t)((s & 1) * 65536);
            const uint32_t bh_base = bb + (uint32_t)((wn + b_row) * 128);
            const uint32_t bl_base = bh_base + 32768;

#pragma unroll
            for (int kk = 0; kk < 4; kk++) {
                const uint32_t a_off = (uint32_t)(((kk * 2 + a_cs) ^ sxor) << 4);
                const uint32_t b_off = (uint32_t)(((kk * 2 + b_cs) ^ sxor) << 4);
                uint32_t ah[4][4], al[4][4];
#pragma unroll
                for (int mi = 0; mi < 4; mi++) {
                    ldm_x4(ah[mi], ah_base + (uint32_t)(mi * 16 * 128) + a_off);
                    ldm_x4(al[mi], al_base + (uint32_t)(mi * 16 * 128) + a_off);
                }
#pragma unroll
                for (int p = 0; p < 4; p++) {
                    uint32_t bh[4], bl[4];
                    ldm_x4(bh, bh_base + (uint32_t)(p * 16 * 128) + b_off);
                    ldm_x4(bl, bl_base + (uint32_t)(p * 16 * 128) + b_off);
#pragma unroll
                    for (int mi = 0; mi < 4; mi++) {
                        mma16816(acc[mi][2 * p],     ah[mi], &bh[0]);
                        mma16816(acc[mi][2 * p + 1], ah[mi], &bh[2]);
                        mma16816(acc[mi][2 * p],     ah[mi], &bl[0]);
                        mma16816(acc[mi][2 * p + 1], ah[mi], &bl[2]);
                        mma16816(acc[mi][2 * p],     al[mi], &bh[0]);
                        mma16816(acc[mi][2 * p + 1], al[mi], &bh[2]);
                    }
                }
            }
            mbar_arrive(emptyA + (uint32_t)((s & 1) * 8));
            asm volatile("bar.sync 1, 256;" ::: "memory");   // consumers done with B(s&1)
        }
        __syncthreads();                                      // s_scale ready

#pragma unroll
        for (int mi = 0; mi < 4; mi++) {
            int rl = wm + mi * 16 + (lane >> 2);
            float s0 = s_scale[rl], s1 = s_scale[rl + 8];
            float* q0 = g_q + (size_t)(m0 + rl) * RDIM + n0 + wn + (lane & 3) * 2;
            float* q1 = q0 + (size_t)8 * RDIM;
#pragma unroll
            for (int ni = 0; ni < 8; ni++) {
                float2 v0 = make_float2(acc[mi][ni][0] * s0, acc[mi][ni][1] * s0);
                float2 v1 = make_float2(acc[mi][ni][2] * s1, acc[mi][ni][3] * s1);
                *(float2*)(q0 + ni * 8) = v0;
                *(float2*)(q1 + ni * 8) = v1;
            }
        }
    } else {
        // ================= PRODUCERS (64 threads) =================
        const int p = tid - 256;                 // 0..63
        const int r0 = p, r1 = p + 64;
        const uint32_t rx0 = (uint32_t)(r0 & 7);
        const uint32_t rx1 = rx0;                // (p+64)&7 == p&7

        auto issue_rawA = [&](int s) {
            asm volatile("mbarrier.arrive.expect_tx.shared.b64 _, [%0], %1;"
                         :: "r"(mbA), "r"(512u) : "memory");
            bulk_ld(smb + RAW_OFF + (uint32_t)(r0 * 256),
                    hidden + ((size_t)(m0 + r0) * HID + s * 64), 256u, mbA);
            bulk_ld(smb + RAW_OFF + (uint32_t)(r1 * 256),
                    hidden + ((size_t)(m0 + r1) * HID + s * 64), 256u, mbA);
        };
        issue_rawA(0);

        float sum0 = 0.f, sum1 = 0.f;
        for (int s = 0; s < NSTAGES; s++) {
            mbar_wait(mbA, (uint32_t)(s & 1));
            if (s >= 2)
                mbar_wait(emptyA + (uint32_t)((s & 1) * 8), (uint32_t)(((s - 2) >> 1) & 1));
            const uint32_t abf = smb + ABF_OFF + (uint32_t)((s & 1) * 32768);
#pragma unroll
            for (int i = 0; i < 16; i++) {
                const int c4 = (i + lane) & 15;
                const uint32_t c = (uint32_t)(c4 >> 1);
                const uint32_t sub = (uint32_t)((c4 & 1) * 8);
                // row r0
                {
                    float4 v = *(const float4*)(sm + RAW_OFF + r0 * 256 + c4 * 16);
                    sum0 += v.x * v.x + v.y * v.y + v.z * v.z + v.w * v.w;
                    const uint32_t dst = abf + (uint32_t)(r0 * 128) + ((c ^ rx0) << 4) + sub;
                    unsigned long long hi = pk4(v.x, v.y, v.z, v.w);
                    unsigned long long lo = pk4(resid(v.x), resid(v.y), resid(v.z), resid(v.w));
                    asm volatile("st.shared.b64 [%0], %1;" :: "r"(dst), "l"(hi) : "memory");
                    asm volatile("st.shared.b64 [%0], %1;" :: "r"(dst + 16384), "l"(lo) : "memory");
                }
                // row r1
                {
                    float4 v = *(const float4*)(sm + RAW_OFF + r1 * 256 + c4 * 16);
                    sum1 += v.x * v.x + v.y * v.y + v.z * v.z + v.w * v.w;
                    const uint32_t dst = abf + (uint32_t)(r1 * 128) + ((c ^ rx1) << 4) + sub;
                    unsigned long long hi = pk4(v.x, v.y, v.z, v.w);
                    unsigned long long lo = pk4(resid(v.x), resid(v.y), resid(v.z), resid(v.w));
                    asm volatile("st.shared.b64 [%0], %1;" :: "r"(dst), "l"(hi) : "memory");
                    asm volatile("st.shared.b64 [%0], %1;" :: "r"(dst + 16384), "l"(lo) : "memory");
                }
            }
            mbar_arrive(fullA + (uint32_t)((s & 1) * 8));   // release: abf visible to consumers
            if (s + 1 < NSTAGES) issue_rawA(s + 1);          // raw fully consumed above
        }
        s_scale[r0] = rsqrtf(sum0 * (1.0f / (float)HID) + 1e-6f);
        s_scale[r1] = rsqrtf(sum1 * (1.0f / (float)HID) + 1e-6f);
        __syncthreads();                                     // pair with consumers' sync
    }
}

// ============================================================
// Kernel 3: scores + causal top-16 + weights (unchanged from R11)
// ============================================================
#define CSWAP(a,b) { if (ti[a] < ti[b]) { int t0=ti[a]; ti[a]=ti[b]; ti[b]=t0; \
                                          float t1=tv[a]; tv[a]=tv[b]; tv[b]=t1; } }

__global__ __launch_bounds__(128) void scores_kernel(const float* __restrict__ lmk,
                                                     float* __restrict__ out) {
    const int n = blockIdx.z;
    const int h = blockIdx.y;
    const int cblk = 127 - blockIdx.x;
    const int pair = threadIdx.x >> 1;
    const int parity = threadIdx.x & 1;
    const int c = cblk * 64 + pair;

    __shared__ __align__(16) float4 sL[DD * 16];
    {
        int d = threadIdx.x;
        const float4* src = (const float4*)(lmk + ((size_t)((n * DD + d) * HH + h) << 6));
#pragma unroll
        for (int e = 0; e < 16; e++) sL[d * 16 + (e ^ (d & 15))] = src[e];
    }
    __syncthreads();

    float4 qv[16];
    const float4* qp = (const float4*)(g_q + ((size_t)(n * CC + c) * RDIM + h * 64));
#pragma unroll
    for (int e = 0; e < 16; e++) qv[e] = qp[e];

    const int v = c >> 6;
    float tv[TOPK];
    int   ti[TOPK];
#pragma unroll
    for (int i = 0; i < TOPK; i++) { tv[i] = -INFINITY; ti[i] = -1; }

    for (int j = parity; j < v; j += 2) {
        const int jx = j & 15;
        float dot = 0.f;
#pragma unroll
        for (int e = 0; e < 16; e++) {
            float4 l = sL[j * 16 + (e ^ jx)];
            dot += qv[e].x * l.x + qv[e].y * l.y + qv[e].z * l.z + qv[e].w * l.w;
        }
        float s = dot * 0.125f;
        if (s > tv[0]) {
            bool done = false;
#pragma unroll
            for (int i = 0; i < TOPK - 1; i++) {
                if (!done) {
                    if (tv[i + 1] < s) { tv[i] = tv[i + 1]; ti[i] = ti[i + 1]; }
                    else               { tv[i] = s; ti[i] = j; done = true; }
                }
            }
            if (!done) { tv[TOPK - 1] = s; ti[TOPK - 1] = j; }
        }
    }

#pragma unroll
    for (int i = 0; i < TOPK / 2; i++) {
        const int k = TOPK - 1 - i;
        float pvH = __shfl_xor_sync(0xffffffffu, tv[k], 1);
        int   piH = __shfl_xor_sync(0xffffffffu, ti[k], 1);
        float pvL = __shfl_xor_sync(0xffffffffu, tv[i], 1);
        int   piL = __shfl_xor_sync(0xffffffffu, ti[i], 1);
        if (pvH > tv[i]) { tv[i] = pvH; ti[i] = piH; }
        if (pvL > tv[k]) { tv[k] = pvL; ti[k] = piL; }
    }

    if (parity == 0) {
        CSWAP(0,1) CSWAP(2,3) CSWAP(4,5) CSWAP(6,7) CSWAP(8,9) CSWAP(10,11) CSWAP(12,13) CSWAP(14,15)
        CSWAP(0,2) CSWAP(1,3) CSWAP(4,6) CSWAP(5,7) CSWAP(8,10) CSWAP(9,11) CSWAP(12,14) CSWAP(13,15)
        CSWAP(1,2) CSWAP(5,6) CSWAP(9,10) CSWAP(13,14)
        CSWAP(0,4) CSWAP(1,5) CSWAP(2,6) CSWAP(3,7) CSWAP(8,12) CSWAP(9,13) CSWAP(10,14) CSWAP(11,15)
        CSWAP(2,4) CSWAP(3,5) CSWAP(10,12) CSWAP(11,13)
        CSWAP(1,2) CSWAP(3,4) CSWAP(5,6) CSWAP(9,10) CSWAP(11,12) CSWAP(13,14)
        CSWAP(0,8) CSWAP(1,9) CSWAP(2,10) CSWAP(3,11) CSWAP(4,12) CSWAP(5,13) CSWAP(6,14) CSWAP(7,15)
        CSWAP(4,8) CSWAP(5,9) CSWAP(6,10) CSWAP(7,11)
        CSWAP(2,4) CSWAP(3,5) CSWAP(6,8) CSWAP(7,9) CSWAP(10,12) CSWAP(11,13)
        CSWAP(1,2) CSWAP(3,4) CSWAP(5,6) CSWAP(7,8) CSWAP(9,10) CSWAP(11,12) CSWAP(13,14)

        const size_t IDX_OFF = (size_t)NB * CC * HH * TOPK;
        size_t base = ((size_t)(n * CC + c) * HH + h) << 4;
        float cum = 0.f;
#pragma unroll
        for (int i = 0; i < TOPK; i++) {
            bool valid = ti[i] >= 0;
            float s = valid ? tv[i] : -INFINITY;
            float sp = (s > 15.0f) ? s : log1pf(expf(s));
            cum += sp;
            out[base + i] = expf(s - cum);
            out[IDX_OFF + base + i] = valid ? (float)ti[i] : 0.0f;
        }
    }
}

// ============================================================
extern "C" void kernel_launch(void* const* d_in, const int* in_sizes, int n_in,
                              void* d_out, int out_size) {
    const float* hidden = (const float*)d_in[0];
    const float* lmk    = (const float*)d_in[1];
    const float* prew   = (const float*)d_in[2];
    const float* W      = (const float*)d_in[3];
    float* out = (float*)d_out;

    split_b_kernel<<<RDIM, 256>>>(W, prew);
    static bool attr_set = false;
    if (!attr_set) {
        cudaFuncSetAttribute(gemm_hmma_kernel,
                             cudaFuncAttributeMaxDynamicSharedMemorySize, SMEM_REQ);
        attr_set = true;
    }
    gemm_hmma_kernel<<<dim3(2, 128), NTHR, SMEM_REQ>>>(hidden);
    scores_kernel<<<dim3(128, HH, NB), 128>>>(lmk, out);
}

// round 15
// speedup vs baseline: 1.3766x; 1.3766x over previous
#include <cuda_runtime.h>
#include <cuda_bf16.h>
#include <math.h>
#include <stdint.h>

#define NB 2
#define CC 8192
#define HID 4096
#define RDIM 512
#define HH 8
#define DD 128
#define TOPK 16
#define NROWS (NB*CC)

// -------- device scratch (packed, stage-contiguous layouts) --------
__device__ __align__(128) uint8_t g_apack[(size_t)128 * 64 * 32768];
__device__ __align__(128) uint8_t g_bpack[(size_t)2 * 64 * 65536];
__device__ float g_scale[NROWS];
__device__ float g_q[(size_t)NROWS * RDIM];
__device__ int g_flag[128];          // per-mtile completion counters (0..2)

// -------- helpers --------
__device__ __forceinline__ unsigned long long pk4(float a, float b, float c, float d) {
    return (unsigned long long)__bfloat16_as_ushort(__float2bfloat16_rn(a))
         | ((unsigned long long)__bfloat16_as_ushort(__float2bfloat16_rn(b)) << 16)
         | ((unsigned long long)__bfloat16_as_ushort(__float2bfloat16_rn(c)) << 32)
         | ((unsigned long long)__bfloat16_as_ushort(__float2bfloat16_rn(d)) << 48);
}
__device__ __forceinline__ float resid(float v) {
    return v - __bfloat162float(__float2bfloat16_rn(v));
}
__device__ __forceinline__ void ldm_x4(uint32_t* r, uint32_t addr) {
    asm volatile("ldmatrix.sync.aligned.m8n8.x4.shared.b16 {%0,%1,%2,%3}, [%4];"
                 : "=r"(r[0]), "=r"(r[1]), "=r"(r[2]), "=r"(r[3]) : "r"(addr));
}
__device__ __forceinline__ void mma16816(float* d, const uint32_t* a, const uint32_t* b) {
    asm volatile("mma.sync.aligned.m16n8k16.row.col.f32.bf16.bf16.f32 "
                 "{%0,%1,%2,%3}, {%4,%5,%6,%7}, {%8,%9}, {%0,%1,%2,%3};"
                 : "+f"(d[0]), "+f"(d[1]), "+f"(d[2]), "+f"(d[3])
                 : "r"(a[0]), "r"(a[1]), "r"(a[2]), "r"(a[3]), "r"(b[0]), "r"(b[1]));
}
__device__ __forceinline__ void mbar_wait(uint32_t a, uint32_t ph) {
    asm volatile("{\n\t.reg .pred P;\n\tWL%=:\n\t"
                 "mbarrier.try_wait.parity.acquire.cta.shared::cta.b64 P, [%0], %1, 0x989680;\n\t"
                 "@!P bra WL%=;\n\t}" :: "r"(a), "r"(ph) : "memory");
}
__device__ __forceinline__ void bulk_ld(uint32_t dst, const void* src, uint32_t bytes, uint32_t mbar) {
    asm volatile("cp.async.bulk.shared::cluster.global.mbarrier::complete_tx::bytes "
                 "[%0], [%1], %2, [%3];" :: "r"(dst), "l"(src), "r"(bytes), "r"(mbar) : "memory");
}

// ============================================================
// Kernel 1: fused RMS sumsq + bf16 hi/lo split -> packed A blocks
// ============================================================
__global__ __launch_bounds__(256) void split_a_kernel(const float* __restrict__ x) {
    const int row = blockIdx.x;
    const int mtile = row >> 7;
    const int r = row & 127;
    const uint32_t rx = (uint32_t)(r & 7);
    const float4* xr = (const float4*)(x + (size_t)row * HID);
    float sum = 0.f;
#pragma unroll
    for (int i = 0; i < 4; i++) {
        const int f = threadIdx.x + i * 256;
        float4 v = xr[f];
        sum += v.x * v.x + v.y * v.y + v.z * v.z + v.w * v.w;
        const int stage = f >> 4;
        const uint32_t c = (uint32_t)((f >> 1) & 7);
        const uint32_t sub = (uint32_t)((f & 1) * 8);
        size_t base = ((size_t)(mtile * 64 + stage)) * 32768
                    + (uint32_t)(r * 128) + ((c ^ rx) << 4) + sub;
        *(unsigned long long*)(g_apack + base)         = pk4(v.x, v.y, v.z, v.w);
        *(unsigned long long*)(g_apack + base + 16384) = pk4(resid(v.x), resid(v.y), resid(v.z), resid(v.w));
    }
#pragma unroll
    for (int o = 16; o; o >>= 1) sum += __shfl_xor_sync(0xffffffffu, sum, o);
    __shared__ float red[8];
    if ((threadIdx.x & 31) == 0) red[threadIdx.x >> 5] = sum;
    __syncthreads();
    if (threadIdx.x < 8) {
        float s = red[threadIdx.x];
#pragma unroll
        for (int o = 4; o; o >>= 1) s += __shfl_xor_sync(0xffu, s, o);
        if (threadIdx.x == 0)
            g_scale[row] = rsqrtf(s * (1.0f / (float)HID) + 1e-6f);
    }
}

// ============================================================
// Kernel 2: fold prew into W rows, split -> packed B blocks.
// Also zeroes the per-mtile flags (runs before gemm every replay).
// ============================================================
__global__ __launch_bounds__(256) void split_b_kernel(const float* __restrict__ W,
                                                      const float* __restrict__ prew) {
    const int row = blockIdx.x;
    if (threadIdx.x == 0 && row < 128) g_flag[row] = 0;
    const int ntile = row >> 8;
    const int r = row & 255;
    const uint32_t rx = (uint32_t)(r & 7);
    const float4* wr = (const float4*)(W + (size_t)row * HID);
    const float4* pr = (const float4*)prew;
#pragma unroll
    for (int i = 0; i < 4; i++) {
        const int f = threadIdx.x + i * 256;
        float4 w = wr[f], p = pr[f];
        w.x *= p.x; w.y *= p.y; w.z *= p.z; w.w *= p.w;
        const int stage = f >> 4;
        const uint32_t c = (uint32_t)((f >> 1) & 7);
        const uint32_t sub = (uint32_t)((f & 1) * 8);
        size_t base = ((size_t)(ntile * 64 + stage)) * 65536
                    + (uint32_t)(r * 128) + ((c ^ rx) << 4) + sub;
        *(unsigned long long*)(g_bpack + base)         = pk4(w.x, w.y, w.z, w.w);
        *(unsigned long long*)(g_bpack + base + 32768) = pk4(resid(w.x), resid(w.y), resid(w.z), resid(w.w));
    }
}

// ============================================================
// Kernel 3: HMMA bf16x3 GEMM, bulk-copy load path (R8/R11 compute,
// + PDL trigger at start, + per-mtile release flag at end)
// ============================================================
#define STG 98304
#define OFF_AH 0
#define OFF_AL 16384
#define OFF_BH 32768
#define OFF_BL 65536
#define SMEM_REQ (2*STG)
#define NSTAGES 64

__global__ void __launch_bounds__(256, 1) gemm_hmma_kernel() {
    extern __shared__ __align__(128) uint8_t sm[];
    __shared__ __align__(8) uint64_t s_mbar[2];
    const uint32_t smb = (uint32_t)__cvta_generic_to_shared(sm);
    const uint32_t mb0 = (uint32_t)__cvta_generic_to_shared(&s_mbar[0]);
    const int tid = threadIdx.x;
    const int lane = tid & 31;
    const int wid = tid >> 5;
    const int mtile = blockIdx.y;
    const int ntile = blockIdx.x;
    const int m0 = mtile * 128;
    const int n0 = ntile * 256;
    const int wm = (wid & 1) * 64;
    const int wn = (wid >> 1) * 64;

    cudaTriggerProgrammaticLaunchCompletion();   // let scores_kernel launch early

    if (tid == 0) {
        asm volatile("mbarrier.init.shared.b64 [%0], 1;" :: "r"(mb0) : "memory");
        asm volatile("mbarrier.init.shared.b64 [%0], 1;" :: "r"(mb0 + 8) : "memory");
    }
    __syncthreads();

    auto issue_load = [&](int s) {
        const uint32_t mb = mb0 + (uint32_t)((s & 1) * 8);
        const uint32_t dst = smb + (uint32_t)((s & 1) * STG);
        asm volatile("mbarrier.arrive.expect_tx.shared.b64 _, [%0], %1;"
                     :: "r"(mb), "r"(98304u) : "memory");
        bulk_ld(dst,         g_apack + ((size_t)(mtile * 64 + s)) * 32768, 32768u, mb);
        bulk_ld(dst + 32768, g_bpack + ((size_t)(ntile * 64 + s)) * 65536, 65536u, mb);
    };

    if (tid == 0) issue_load(0);

    float acc[4][8][4];
#pragma unroll
    for (int i = 0; i < 4; i++)
#pragma unroll
        for (int j = 0; j < 8; j++)
#pragma unroll
            for (int q = 0; q < 4; q++) acc[i][j][q] = 0.f;

    const int a_row = lane & 15;
    const int a_cs  = lane >> 4;
    const int b_row = (lane & 7) + ((lane >> 4) << 3);
    const int b_cs  = (lane >> 3) & 1;
    const int sxor  = lane & 7;

    for (int s = 0; s < NSTAGES; s++) {
        if (s + 1 < NSTAGES && tid == 0) issue_load(s + 1);
        mbar_wait(mb0 + (uint32_t)((s & 1) * 8), (uint32_t)((s >> 1) & 1));

        const uint32_t base = smb + (s & 1) * STG;
        const uint32_t ah_base = base + OFF_AH + (uint32_t)((wm + a_row) * 128);
        const uint32_t al_base = base + OFF_AL + (uint32_t)((wm + a_row) * 128);
        const uint32_t bh_base = base + OFF_BH + (uint32_t)((wn + b_row) * 128);
        const uint32_t bl_base = base + OFF_BL + (uint32_t)((wn + b_row) * 128);

#pragma unroll
        for (int kk = 0; kk < 4; kk++) {
            const uint32_t a_off = (uint32_t)(((kk * 2 + a_cs) ^ sxor) << 4);
            const uint32_t b_off = (uint32_t)(((kk * 2 + b_cs) ^ sxor) << 4);
            uint32_t ah[4][4], al[4][4];
#pragma unroll
            for (int mi = 0; mi < 4; mi++) {
                ldm_x4(ah[mi], ah_base + (uint32_t)(mi * 16 * 128) + a_off);
                ldm_x4(al[mi], al_base + (uint32_t)(mi * 16 * 128) + a_off);
            }
#pragma unroll
            for (int p = 0; p < 4; p++) {
                uint32_t bh[4], bl[4];
                ldm_x4(bh, bh_base + (uint32_t)(p * 16 * 128) + b_off);
                ldm_x4(bl, bl_base + (uint32_t)(p * 16 * 128) + b_off);
#pragma unroll
                for (int mi = 0; mi < 4; mi++) {
                    mma16816(acc[mi][2 * p],     ah[mi], &bh[0]);
                    mma16816(acc[mi][2 * p + 1], ah[mi], &bh[2]);
                    mma16816(acc[mi][2 * p],     ah[mi], &bl[0]);
                    mma16816(acc[mi][2 * p + 1], ah[mi], &bl[2]);
                    mma16816(acc[mi][2 * p],     al[mi], &bh[0]);
                    mma16816(acc[mi][2 * p + 1], al[mi], &bh[2]);
                }
            }
        }
        __syncthreads();
    }

#pragma unroll
    for (int mi = 0; mi < 4; mi++) {
        int r0 = m0 + wm + mi * 16 + (lane >> 2);
        float s0 = g_scale[r0], s1 = g_scale[r0 + 8];
        float* q0 = g_q + (size_t)r0 * RDIM + n0 + wn + (lane & 3) * 2;
        float* q1 = q0 + (size_t)8 * RDIM;
#pragma unroll
        for (int ni = 0; ni < 8; ni++) {
            float2 v0 = make_float2(acc[mi][ni][0] * s0, acc[mi][ni][1] * s0);
            float2 v1 = make_float2(acc[mi][ni][2] * s1, acc[mi][ni][3] * s1);
            *(float2*)(q0 + ni * 8) = v0;
            *(float2*)(q1 + ni * 8) = v1;
        }
    }

    // release: publish this (mtile, ntile) slice of g_q
    __threadfence();
    __syncthreads();
    if (tid == 0) atomicAdd(&g_flag[mtile], 1);
}

// ============================================================
// Kernel 4: scores + causal top-16 + weights (R11 compute,
// + flag spin before reading g_q)
// ============================================================
#define CSWAP(a,b) { if (ti[a] < ti[b]) { int t0=ti[a]; ti[a]=ti[b]; ti[b]=t0; \
                                          float t1=tv[a]; tv[a]=tv[b]; tv[b]=t1; } }

__global__ __launch_bounds__(128) void scores_kernel(const float* __restrict__ lmk,
                                                     float* __restrict__ out) {
    const int n = blockIdx.z;
    const int h = blockIdx.y;
    const int cblk = 127 - blockIdx.x;          // high-v blocks first
    const int pair = threadIdx.x >> 1;
    const int parity = threadIdx.x & 1;
    const int c = cblk * 64 + pair;

    __shared__ __align__(16) float4 sL[DD * 16];
    {
        int d = threadIdx.x;
        const float4* src = (const float4*)(lmk + ((size_t)((n * DD + d) * HH + h) << 6));
#pragma unroll
        for (int e = 0; e < 16; e++) sL[d * 16 + (e ^ (d & 15))] = src[e];
    }

    // wait for this block's g_q tile (both ntile CTAs of mtile)
    if (threadIdx.x == 0) {
        const int mt = n * 64 + (cblk >> 1);
        int v;
        do {
            asm volatile("ld.acquire.gpu.global.b32 %0, [%1];" : "=r"(v) : "l"(g_flag + mt) : "memory");
            if (v < 2) __nanosleep(256);
        } while (v < 2);
    }
    __syncthreads();

    float4 qv[16];
    const float4* qp = (const float4*)(g_q + ((size_t)(n * CC + c) * RDIM + h * 64));
#pragma unroll
    for (int e = 0; e < 16; e++) qv[e] = qp[e];

    const int v = c >> 6;
    float tv[TOPK];
    int   ti[TOPK];
#pragma unroll
    for (int i = 0; i < TOPK; i++) { tv[i] = -INFINITY; ti[i] = -1; }

    for (int j = parity; j < v; j += 2) {
        const int jx = j & 15;
        float dot = 0.f;
#pragma unroll
        for (int e = 0; e < 16; e++) {
            float4 l = sL[j * 16 + (e ^ jx)];
            dot += qv[e].x * l.x + qv[e].y * l.y + qv[e].z * l.z + qv[e].w * l.w;
        }
        float s = dot * 0.125f;
        if (s > tv[0]) {
            bool done = false;
#pragma unroll
            for (int i = 0; i < TOPK - 1; i++) {
                if (!done) {
                    if (tv[i + 1] < s) { tv[i] = tv[i + 1]; ti[i] = ti[i + 1]; }
                    else               { tv[i] = s; ti[i] = j; done = true; }
                }
            }
            if (!done) { tv[TOPK - 1] = s; ti[TOPK - 1] = j; }
        }
    }

#pragma unroll
    for (int i = 0; i < TOPK / 2; i++) {
        const int k = TOPK - 1 - i;
        float pvH = __shfl_xor_sync(0xffffffffu, tv[k], 1);
        int   piH = __shfl_xor_sync(0xffffffffu, ti[k], 1);
        float pvL = __shfl_xor_sync(0xffffffffu, tv[i], 1);
        int   piL = __shfl_xor_sync(0xffffffffu, ti[i], 1);
        if (pvH > tv[i]) { tv[i] = pvH; ti[i] = piH; }
        if (pvL > tv[k]) { tv[k] = pvL; ti[k] = piL; }
    }

    if (parity == 0) {
        CSWAP(0,1) CSWAP(2,3) CSWAP(4,5) CSWAP(6,7) CSWAP(8,9) CSWAP(10,11) CSWAP(12,13) CSWAP(14,15)
        CSWAP(0,2) CSWAP(1,3) CSWAP(4,6) CSWAP(5,7) CSWAP(8,10) CSWAP(9,11) CSWAP(12,14) CSWAP(13,15)
        CSWAP(1,2) CSWAP(5,6) CSWAP(9,10) CSWAP(13,14)
        CSWAP(0,4) CSWAP(1,5) CSWAP(2,6) CSWAP(3,7) CSWAP(8,12) CSWAP(9,13) CSWAP(10,14) CSWAP(11,15)
        CSWAP(2,4) CSWAP(3,5) CSWAP(10,12) CSWAP(11,13)
        CSWAP(1,2) CSWAP(3,4) CSWAP(5,6) CSWAP(9,10) CSWAP(11,12) CSWAP(13,14)
        CSWAP(0,8) CSWAP(1,9) CSWAP(2,10) CSWAP(3,11) CSWAP(4,12) CSWAP(5,13) CSWAP(6,14) CSWAP(7,15)
        CSWAP(4,8) CSWAP(5,9) CSWAP(6,10) CSWAP(7,11)
        CSWAP(2,4) CSWAP(3,5) CSWAP(6,8) CSWAP(7,9) CSWAP(10,12) CSWAP(11,13)
        CSWAP(1,2) CSWAP(3,4) CSWAP(5,6) CSWAP(7,8) CSWAP(9,10) CSWAP(11,12) CSWAP(13,14)

        const size_t IDX_OFF = (size_t)NB * CC * HH * TOPK;
        size_t base = ((size_t)(n * CC + c) * HH + h) << 4;
        float cum = 0.f;
#pragma unroll
        for (int i = 0; i < TOPK; i++) {
            bool valid = ti[i] >= 0;
            float s = valid ? tv[i] : -INFINITY;
            float sp = (s > 15.0f) ? s : log1pf(expf(s));
            cum += sp;
            out[base + i] = expf(s - cum);
            out[IDX_OFF + base + i] = valid ? (float)ti[i] : 0.0f;
        }
    }
}

// ============================================================
extern "C" void kernel_launch(void* const* d_in, const int* in_sizes, int n_in,
                              void* d_out, int out_size) {
    const float* hidden = (const float*)d_in[0];
    const float* lmk    = (const float*)d_in[1];
    const float* prew   = (const float*)d_in[2];
    const float* W      = (const float*)d_in[3];
    float* out = (float*)d_out;

    split_a_kernel<<<NROWS, 256>>>(hidden);
    split_b_kernel<<<RDIM, 256>>>(W, prew);
    static bool attr_set = false;
    if (!attr_set) {
        cudaFuncSetAttribute(gemm_hmma_kernel,
                             cudaFuncAttributeMaxDynamicSharedMemorySize, SMEM_REQ);
        attr_set = true;
    }
    gemm_hmma_kernel<<<dim3(2, 128), 256, SMEM_REQ>>>();

    // scores: PDL launch — may start while gemm is still running
    cudaLaunchConfig_t cfg = {};
    cfg.gridDim = dim3(128, HH, NB);
    cfg.blockDim = dim3(128);
    cfg.dynamicSmemBytes = 0;
    cfg.stream = 0;
    cudaLaunchAttribute attrs[1];
    attrs[0].id = cudaLaunchAttributeProgrammaticStreamSerialization;
    attrs[0].val.programmaticStreamSerializationAllowed = 1;
    cfg.attrs = attrs;
    cfg.numAttrs = 1;
    cudaLaunchKernelEx(&cfg, scores_kernel, lmk, out);
}